// round 4
// baseline (speedup 1.0000x reference)
#include <cuda_runtime.h>
#include <stdint.h>
#include <math.h>

#define NN   8
#define CC   256
#define HH   100
#define WWW  252
#define HWP  (HH*WWW)        // 25200
#define SS   2520            // int(HW*0.1)
#define KCL  315             // ceil(S*0.125)
#define KNNK 10
#define NS   (NN*SS)         // 20160

// ---------------- scratch (static __device__ -> allocation-free) ----------------
__device__ unsigned long long g_keys[NN*HWP];        // 1.6 MB
__device__ int   g_topidx[NS];
__device__ float g_conf[NS];
__device__ float g_tokens[NS*CC];                    // 20.6 MB
__device__ float g_sq[NS];
__device__ float g_dist[NN*SS*SS];                   // 203 MB
__device__ unsigned int g_distmax[NN];
__device__ float g_density[NS];
__device__ float g_noise[NS];
__device__ float g_cscore[NS];
__device__ int   g_centers[NN*KCL];
__device__ int   g_cluster[NS];
__device__ float g_allw[NN*KCL];
__device__ float g_merged[NN*KCL*CC];                // 2.6 MB
__device__ int   g_isego[NN];

// ---------------- small init kernels ----------------
__global__ void k_zero_small() {
    int i = blockIdx.x * blockDim.x + threadIdx.x;   // grid covers NN*KCL*CC = 645120
    g_merged[i] = 0.f;
    if (i < NN*KCL) g_allw[i] = 0.f;
    if (i < NN)     g_distmax[i] = 0u;
}

__global__ void k_ego_mask(const int* __restrict__ rl, int nrec) {
    if (threadIdx.x == 0 && blockIdx.x == 0) {
        for (int i = 0; i < NN; i++) g_isego[i] = 0;
        int s = 0;
        for (int i = 0; i < nrec; i++) { if (s >= 0 && s < NN) g_isego[s] = 1; s += rl[i]; }
    }
}

// ---------------- score MLP GEMM (M=256 out-ch, N=64 pixels/block, K=256) ----------------
// h1 = relu(w1 @ x + b1); score = sigmoid(w2·h1 + b2) * dis; key = (bits(score)<<32)|~p
#define SG_TN 64
#define SG_KC 32
__global__ __launch_bounds__(256, 2)
void k_score(const float* __restrict__ x, const float* __restrict__ w1,
             const float* __restrict__ b1, const float* __restrict__ w2,
             const float* __restrict__ b2, const float* __restrict__ dis)
{
    int n  = blockIdx.y;
    int p0 = blockIdx.x * SG_TN;
    __shared__ float As[SG_KC][CC];       // w1^T chunk: 32KB
    __shared__ float Bs[SG_KC][SG_TN];    // x chunk: 8KB
    __shared__ float red[16][SG_TN];      // 4KB
    int tid = threadIdx.x;
    int tx = tid & 15;       // pixel group (4 pixels)
    int ty = tid >> 4;       // m group (16 contiguous rows)

    float acc[16][4];
    #pragma unroll
    for (int r = 0; r < 16; r++)
        #pragma unroll
        for (int j = 0; j < 4; j++) acc[r][j] = 0.f;

    const float* xn = x + (size_t)n * CC * HWP;

    for (int k0 = 0; k0 < CC; k0 += SG_KC) {
        // load As[kk][d] = w1[d][k0+kk]
        for (int t = tid; t < CC * (SG_KC/4); t += 256) {
            int d  = t >> 3;            // /(SG_KC/4)=8
            int kq = t & 7;
            float4 v = *(const float4*)(w1 + (size_t)d * CC + k0 + kq*4);
            As[kq*4+0][d] = v.x; As[kq*4+1][d] = v.y;
            As[kq*4+2][d] = v.z; As[kq*4+3][d] = v.w;
        }
        // load Bs[kk][pp] = x[n][k0+kk][p0+pp]
        for (int t = tid; t < SG_KC * (SG_TN/4); t += 256) {
            int kk = t >> 4;            // /(SG_TN/4)=16
            int pq = t & 15;
            int p  = p0 + pq*4;
            float4 v;
            const float* rowp = xn + (size_t)(k0+kk) * HWP;
            if (p + 4 <= HWP) v = *(const float4*)(rowp + p);
            else {
                v.x = (p+0 < HWP) ? rowp[p+0] : 0.f;
                v.y = (p+1 < HWP) ? rowp[p+1] : 0.f;
                v.z = (p+2 < HWP) ? rowp[p+2] : 0.f;
                v.w = (p+3 < HWP) ? rowp[p+3] : 0.f;
            }
            Bs[kk][pq*4+0] = v.x; Bs[kk][pq*4+1] = v.y;
            Bs[kk][pq*4+2] = v.z; Bs[kk][pq*4+3] = v.w;
        }
        __syncthreads();
        #pragma unroll
        for (int kk = 0; kk < SG_KC; kk++) {
            float a[16];
            *(float4*)(a+0)  = *(float4*)&As[kk][ty*16+0];
            *(float4*)(a+4)  = *(float4*)&As[kk][ty*16+4];
            *(float4*)(a+8)  = *(float4*)&As[kk][ty*16+8];
            *(float4*)(a+12) = *(float4*)&As[kk][ty*16+12];
            float4 bf = *(float4*)&Bs[kk][tx*4];
            float bb[4] = {bf.x, bf.y, bf.z, bf.w};
            #pragma unroll
            for (int r = 0; r < 16; r++)
                #pragma unroll
                for (int j = 0; j < 4; j++) acc[r][j] += a[r] * bb[j];
        }
        __syncthreads();
    }

    // epilogue: +b1, relu, *w2, reduce over d
    float part[4] = {0.f, 0.f, 0.f, 0.f};
    #pragma unroll
    for (int r = 0; r < 16; r++) {
        int d = ty*16 + r;
        float bbv = b1[d], wwv = w2[d];
        #pragma unroll
        for (int j = 0; j < 4; j++) {
            float h = acc[r][j] + bbv;
            h = h > 0.f ? h : 0.f;
            part[j] += h * wwv;
        }
    }
    #pragma unroll
    for (int j = 0; j < 4; j++) red[ty][tx*4+j] = part[j];
    __syncthreads();
    if (tid < SG_TN) {
        float s = 0.f;
        #pragma unroll
        for (int r = 0; r < 16; r++) s += red[r][tid];
        int p = p0 + tid;
        if (p < HWP) {
            float z  = s + b2[0];
            float sc = 1.f / (1.f + expf(-z));
            sc *= dis[(size_t)n*HWP + p];
            unsigned int bits = __float_as_uint(sc);
            g_keys[(size_t)n*HWP + p] =
                ((unsigned long long)bits << 32) | (unsigned int)(~(unsigned int)p);
        }
    }
}

// ---------------- bitonic ascending sort in shared (n power of 2) ----------------
__device__ __forceinline__ void bitonic_asc(unsigned long long* buf, int n, int tid, int nth) {
    for (int k2 = 2; k2 <= n; k2 <<= 1)
        for (int j = k2 >> 1; j > 0; j >>= 1) {
            __syncthreads();
            for (int i = tid; i < n; i += nth) {
                int ixj = i ^ j;
                if (ixj > i) {
                    unsigned long long a = buf[i], b = buf[ixj];
                    bool up = ((i & k2) == 0);
                    if (up ? (a > b) : (a < b)) { buf[i] = b; buf[ixj] = a; }
                }
            }
        }
    __syncthreads();
}

// ---------------- exact top-S per image: radix select + gather + bitonic ----------------
__global__ __launch_bounds__(1024)
void k_topk() {
    int b = blockIdx.x;
    const unsigned long long* keys = g_keys + (size_t)b * HWP;
    __shared__ unsigned int hist[256];
    __shared__ unsigned long long sh_prefix;
    __shared__ int sh_R, sh_cnt;
    __shared__ unsigned long long buf[4096];
    int tid = threadIdx.x;
    if (tid == 0) { sh_prefix = 0ULL; sh_R = SS; sh_cnt = 0; }

    for (int byte = 7; byte >= 0; byte--) {
        if (tid < 256) hist[tid] = 0u;
        __syncthreads();
        int shift = byte * 8;
        unsigned long long pref = sh_prefix;
        for (int i = tid; i < HWP; i += 1024) {
            unsigned long long k = keys[i];
            if (byte == 7 || (k >> (shift+8)) == (pref >> (shift+8)))
                atomicAdd(&hist[(unsigned)(k >> shift) & 0xFFu], 1u);
        }
        __syncthreads();
        if (tid == 0) {
            int R = sh_R; long long cum = 0; int chosen = 0;
            for (int v = 255; v >= 0; v--) {
                cum += hist[v];
                if (cum >= R) { chosen = v; sh_R = R - (int)(cum - hist[v]); break; }
            }
            sh_prefix = pref | ((unsigned long long)chosen << shift);
        }
        __syncthreads();
    }
    unsigned long long T = sh_prefix;
    for (int i = tid; i < 4096; i += 1024) buf[i] = 0ULL;
    __syncthreads();
    for (int i = tid; i < HWP; i += 1024) {
        unsigned long long k = keys[i];
        if (k >= T) { int pos = atomicAdd(&sh_cnt, 1); if (pos < 4096) buf[pos] = k; }
    }
    __syncthreads();
    bitonic_asc(buf, 4096, tid, 1024);
    for (int s = tid; s < SS; s += 1024) {
        unsigned long long k = buf[4095 - s];
        g_topidx[b*SS + s] = (int)(~(unsigned int)k);
        g_conf  [b*SS + s] = __uint_as_float((unsigned int)(k >> 32));
    }
}

// ---------------- gather tokens + layernorm + *conf + sumsq ----------------
__global__ void k_gather_ln(const float* __restrict__ x) {
    int b = blockIdx.y, s = blockIdx.x;
    int c = threadIdx.x;  // 256
    __shared__ float sh[256];
    int   pix  = g_topidx[b*SS + s];
    float conf = g_conf[b*SS + s];
    float v = x[((size_t)b*CC + c)*HWP + pix];

    sh[c] = v; __syncthreads();
    for (int st = 128; st > 0; st >>= 1) { if (c < st) sh[c] += sh[c+st]; __syncthreads(); }
    float mu = sh[0] * (1.f/256.f);
    __syncthreads();

    float dv = v - mu;
    sh[c] = dv * dv; __syncthreads();
    for (int st = 128; st > 0; st >>= 1) { if (c < st) sh[c] += sh[c+st]; __syncthreads(); }
    float var = sh[0] * (1.f/256.f);
    __syncthreads();

    float t = dv / sqrtf(var + 1e-5f) * conf;
    g_tokens[((size_t)b*SS + s)*CC + c] = t;

    sh[c] = t * t; __syncthreads();
    for (int st = 128; st > 0; st >>= 1) { if (c < st) sh[c] += sh[c+st]; __syncthreads(); }
    if (c == 0) g_sq[b*SS + s] = sh[0];
}

// ---------------- threefry2x32 noise (exact jax.random.uniform(key(1),(N,S))) ----------------
__device__ __forceinline__ unsigned int rotl32(unsigned int x, int r) {
    return (x << r) | (x >> (32 - r));
}
__global__ void k_noise() {
    int i = blockIdx.x * blockDim.x + threadIdx.x;
    const int half = NS / 2;  // 10080
    if (i >= half) return;
    unsigned int x0 = (unsigned int)i, x1 = (unsigned int)(i + half);
    const unsigned int ks0 = 0u, ks1 = 1u, ks2 = 0x1BD11BDAu ^ 0u ^ 1u;
    x0 += ks0; x1 += ks1;
#define RG4(a0,a1,a2,a3) \
    x0 += x1; x1 = rotl32(x1,a0); x1 ^= x0; \
    x0 += x1; x1 = rotl32(x1,a1); x1 ^= x0; \
    x0 += x1; x1 = rotl32(x1,a2); x1 ^= x0; \
    x0 += x1; x1 = rotl32(x1,a3); x1 ^= x0;
    RG4(13,15,26,6)  x0 += ks1; x1 += ks2 + 1u;
    RG4(17,29,16,24) x0 += ks2; x1 += ks0 + 2u;
    RG4(13,15,26,6)  x0 += ks0; x1 += ks1 + 3u;
    RG4(17,29,16,24) x0 += ks1; x1 += ks2 + 4u;
    RG4(13,15,26,6)  x0 += ks2; x1 += ks0 + 5u;
#undef RG4
    g_noise[i]        = __uint_as_float((x0 >> 9) | 0x3f800000u) - 1.0f;
    g_noise[i + half] = __uint_as_float((x1 >> 9) | 0x3f800000u) - 1.0f;
}

// ---------------- distance matrix GEMM (symmetric, 128x128 tiles) ----------------
#define DG_T  128
#define DG_KC 16
__global__ __launch_bounds__(256, 2)
void k_dist() {
    int b  = blockIdx.z;
    int bi = blockIdx.y, bj = blockIdx.x;
    if (bj > bi) return;  // symmetry
    int i0 = bi * DG_T, j0 = bj * DG_T;
    __shared__ float As[DG_KC][DG_T];
    __shared__ float Bs[DG_KC][DG_T];
    int tid = threadIdx.x;
    int tx = tid & 15, ty = tid >> 4;

    float acc[8][8];
    #pragma unroll
    for (int r = 0; r < 8; r++)
        #pragma unroll
        for (int c = 0; c < 8; c++) acc[r][c] = 0.f;

    const float* tok = g_tokens + (size_t)b * SS * CC;
    for (int k0 = 0; k0 < CC; k0 += DG_KC) {
        for (int t = tid; t < DG_T * (DG_KC/4); t += 256) {
            int row = t >> 2, kq = t & 3;
            int gi = i0 + row;
            float4 v = (gi < SS) ? *(const float4*)(tok + (size_t)gi*CC + k0 + kq*4)
                                 : make_float4(0.f,0.f,0.f,0.f);
            As[kq*4+0][row] = v.x; As[kq*4+1][row] = v.y;
            As[kq*4+2][row] = v.z; As[kq*4+3][row] = v.w;
            int gj = j0 + row;
            float4 w = (gj < SS) ? *(const float4*)(tok + (size_t)gj*CC + k0 + kq*4)
                                 : make_float4(0.f,0.f,0.f,0.f);
            Bs[kq*4+0][row] = w.x; Bs[kq*4+1][row] = w.y;
            Bs[kq*4+2][row] = w.z; Bs[kq*4+3][row] = w.w;
        }
        __syncthreads();
        #pragma unroll
        for (int kk = 0; kk < DG_KC; kk++) {
            float a[8], bb[8];
            *(float4*)(a+0)  = *(float4*)&As[kk][ty*8+0];
            *(float4*)(a+4)  = *(float4*)&As[kk][ty*8+4];
            *(float4*)(bb+0) = *(float4*)&Bs[kk][tx*8+0];
            *(float4*)(bb+4) = *(float4*)&Bs[kk][tx*8+4];
            #pragma unroll
            for (int r = 0; r < 8; r++)
                #pragma unroll
                for (int c = 0; c < 8; c++) acc[r][c] += a[r] * bb[c];
        }
        __syncthreads();
    }

    float bmax = 0.f;
    #pragma unroll
    for (int r = 0; r < 8; r++) {
        int i = i0 + ty*8 + r;
        if (i >= SS) continue;
        float sqi = g_sq[b*SS + i];
        #pragma unroll
        for (int c = 0; c < 8; c++) {
            int j = j0 + tx*8 + c;
            if (j >= SS) continue;
            float d2 = sqi + g_sq[b*SS + j] - 2.f * acc[r][c];
            float d  = sqrtf(fmaxf(d2, 1e-12f)) * 0.0625f;  // /sqrt(256)
            g_dist[((size_t)b*SS + i)*SS + j] = d;
            if (bi != bj) g_dist[((size_t)b*SS + j)*SS + i] = d;
            bmax = fmaxf(bmax, d);
        }
    }
    // block max -> atomicMax (positive float bits are order-preserving)
    #pragma unroll
    for (int off = 16; off; off >>= 1) bmax = fmaxf(bmax, __shfl_xor_sync(0xFFFFFFFFu, bmax, off));
    __shared__ float wmax[8];
    int lane = tid & 31, wid = tid >> 5;
    if (lane == 0) wmax[wid] = bmax;
    __syncthreads();
    if (tid == 0) {
        float m = 0.f;
        for (int w = 0; w < 8; w++) m = fmaxf(m, wmax[w]);
        atomicMax(&g_distmax[b], __float_as_uint(m));
    }
}

// ---------------- KNN density (warp per row) ----------------
__global__ void k_knn() {
    int gw = (blockIdx.x * blockDim.x + threadIdx.x) >> 5;
    int lane = threadIdx.x & 31;
    if (gw >= NS) return;
    int b = gw / SS, i = gw % SS;
    const float* row = g_dist + ((size_t)b*SS + i)*SS;

    float top[KNNK];
    #pragma unroll
    for (int t = 0; t < KNNK; t++) top[t] = 3.4e38f;
    for (int j = lane; j < SS; j += 32) {
        float d = row[j];
        if (d < top[KNNK-1]) {
            top[KNNK-1] = d;
            #pragma unroll
            for (int t = KNNK-1; t > 0; t--)
                if (top[t] < top[t-1]) { float tmp = top[t-1]; top[t-1] = top[t]; top[t] = tmp; }
        }
    }
    // merge 32 sorted lists -> 10 smallest overall
    int ptr = 0;
    float sumsq = 0.f;
    for (int t = 0; t < KNNK; t++) {
        float cand = (ptr < KNNK) ? top[ptr] : 3.4e38f;
        float m = cand;
        #pragma unroll
        for (int off = 16; off; off >>= 1) m = fminf(m, __shfl_xor_sync(0xFFFFFFFFu, m, off));
        sumsq += m * m;
        unsigned bal = __ballot_sync(0xFFFFFFFFu, cand == m);
        int src = __ffs(bal) - 1;
        if (lane == src) ptr++;
    }
    if (lane == 0)
        g_density[gw] = expf(-(sumsq * (1.f/KNNK))) + g_noise[gw] * 1e-6f;
}

// ---------------- parent distance + cscore (warp per row) ----------------
__global__ void k_parent() {
    int gw = (blockIdx.x * blockDim.x + threadIdx.x) >> 5;
    int lane = threadIdx.x & 31;
    if (gw >= NS) return;
    int b = gw / SS, i = gw % SS;
    float di   = g_density[gw];
    float dmax = __uint_as_float(g_distmax[b]);
    const float* row  = g_dist + ((size_t)b*SS + i)*SS;
    const float* dens = g_density + b*SS;
    float acc = dmax;
    for (int j = lane; j < SS; j += 32)
        if (dens[j] > di) acc = fminf(acc, row[j]);
    #pragma unroll
    for (int off = 16; off; off >>= 1) acc = fminf(acc, __shfl_xor_sync(0xFFFFFFFFu, acc, off));
    if (lane == 0) g_cscore[gw] = acc * di;
}

// ---------------- cluster centers: exact top-K of cscore ----------------
__global__ __launch_bounds__(1024)
void k_centers() {
    int b = blockIdx.x;
    __shared__ unsigned long long buf[4096];
    int tid = threadIdx.x;
    for (int i = tid; i < 4096; i += 1024) {
        unsigned long long key = 0ULL;
        if (i < SS) {
            unsigned int bits = __float_as_uint(g_cscore[b*SS + i]);
            key = ((unsigned long long)bits << 32) | (unsigned int)(~(unsigned int)i);
        }
        buf[i] = key;
    }
    __syncthreads();
    bitonic_asc(buf, 4096, tid, 1024);
    for (int k = tid; k < KCL; k += 1024) {
        unsigned long long key = buf[4095 - k];
        g_centers[b*KCL + k] = (int)(~(unsigned int)key);
    }
}

// ---------------- cluster assignment (argmin over centers, first-min tie-break) ----------------
__global__ void k_assign() {
    int b = blockIdx.y;
    int s = blockIdx.x * blockDim.x + threadIdx.x;
    __shared__ int cs[KCL];
    for (int t = threadIdx.x; t < KCL; t += blockDim.x) cs[t] = g_centers[b*KCL + t];
    __syncthreads();
    if (s >= SS) return;
    float best = 3.4e38f; int bk = 0;
    for (int k = 0; k < KCL; k++) {
        float d = g_dist[((size_t)b*SS + cs[k])*SS + s];
        if (d < best) { best = d; bk = k; }
    }
    g_cluster[b*SS + s] = bk;
}

__global__ void k_override() {
    int b = blockIdx.x, k = threadIdx.x;
    if (k < KCL) g_cluster[b*SS + g_centers[b*KCL + k]] = k;
}

// ---------------- merge: confidence-weighted average per cluster ----------------
__global__ void k_weights() {
    int i = blockIdx.x * blockDim.x + threadIdx.x;
    if (i < NS) atomicAdd(&g_allw[(i / SS)*KCL + g_cluster[i]], g_conf[i]);
}

__global__ void k_merge() {
    int b = blockIdx.y, s = blockIdx.x, c = threadIdx.x;
    int cl = g_cluster[b*SS + s];
    float nw = g_conf[b*SS + s] / (g_allw[b*KCL + cl] + 1e-6f);
    atomicAdd(&g_merged[((size_t)b*KCL + cl)*CC + c],
              g_tokens[((size_t)b*SS + s)*CC + c] * nw);
}

// ---------------- scatter + ego copy ----------------
__global__ void k_scatter(float* __restrict__ out) {
    int b = blockIdx.y, s = blockIdx.x, c = threadIdx.x;
    if (g_isego[b]) return;
    int pix = g_topidx[b*SS + s];
    int cl  = g_cluster[b*SS + s];
    out[((size_t)b*CC + c)*HWP + pix] = g_merged[((size_t)b*KCL + cl)*CC + c];
}

__global__ void k_egocopy(const float* __restrict__ x, float* __restrict__ out) {
    size_t idx = (size_t)blockIdx.x * blockDim.x + threadIdx.x;
    if (idx >= (size_t)NN * CC * HWP) return;
    int b = (int)(idx / ((size_t)CC * HWP));
    if (g_isego[b]) out[idx] = x[idx];
}

// ---------------- launch ----------------
extern "C" void kernel_launch(void* const* d_in, const int* in_sizes, int n_in,
                              void* d_out, int out_size) {
    const float* x   = (const float*)d_in[0];
    const float* w1  = (const float*)d_in[1];
    const float* b1  = (const float*)d_in[2];
    const float* w2  = (const float*)d_in[3];
    const float* b2  = (const float*)d_in[4];
    const float* dis = (const float*)d_in[5];
    const int*   rl  = (const int*)d_in[6];
    int nrec = in_sizes[6];
    float* out = (float*)d_out;

    cudaMemsetAsync(d_out, 0, (size_t)out_size * sizeof(float), 0);
    k_zero_small<<<NN*KCL, CC>>>();                              // 645120 threads exactly
    k_ego_mask<<<1, 32>>>(rl, nrec);

    k_score<<<dim3((HWP + SG_TN - 1)/SG_TN, NN), 256>>>(x, w1, b1, w2, b2, dis);
    k_topk<<<NN, 1024>>>();
    k_gather_ln<<<dim3(SS, NN), 256>>>(x);
    k_noise<<<(NS/2 + 255)/256, 256>>>();
    k_dist<<<dim3((SS + DG_T - 1)/DG_T, (SS + DG_T - 1)/DG_T, NN), 256>>>();
    k_knn<<<(NS*32 + 255)/256, 256>>>();
    k_parent<<<(NS*32 + 255)/256, 256>>>();
    k_centers<<<NN, 1024>>>();
    k_assign<<<dim3((SS + 255)/256, NN), 256>>>();
    k_override<<<NN, 320>>>();
    k_weights<<<(NS + 255)/256, 256>>>();
    k_merge<<<dim3(SS, NN), 256>>>();
    k_scatter<<<dim3(SS, NN), 256>>>(out);
    k_egocopy<<<(unsigned)(((size_t)NN*CC*HWP + 255)/256), 256>>>(x, out);
}